// round 5
// baseline (speedup 1.0000x reference)
#include <cuda_runtime.h>
#include <math.h>
#include <stdint.h>

#define B_  2
#define S_  2048
#define E_  1024
#define H_  16
#define HD_ 64

// Scratch (allocation-free: __device__ globals)
__device__ float g_Q[B_*H_*S_*HD_];   // tf32-rounded, pre-scaled by 0.125*log2(e)
__device__ float g_K[B_*H_*S_*HD_];   // tf32-rounded
__device__ float g_V[B_*H_*S_*HD_];   // tf32-rounded
__device__ float g_O[B_*S_*E_];       // attention out, tf32-rounded (proj A input)
__device__ float g_Xr[B_*S_*E_];      // tf32-rounded x
__device__ float g_Wq[3*E_*E_];       // tf32-rounded w_qkv
__device__ float g_Wp[E_*E_];         // tf32-rounded w_proj

// ============================================================================
// PTX helpers (plain sm_80+ ISA — no 'a'-suffix features)
// ============================================================================
__device__ __forceinline__ float tf32_rna(float x) {
    uint32_t r;
    asm("cvt.rna.tf32.f32 %0, %1;" : "=r"(r) : "f"(x));
    return __uint_as_float(r);
}

__device__ __forceinline__ void mma_tf32(float4& d,
                                         uint32_t a0, uint32_t a1, uint32_t a2, uint32_t a3,
                                         uint32_t b0, uint32_t b1)
{
    asm volatile(
        "mma.sync.aligned.m16n8k8.row.col.f32.tf32.tf32.f32 "
        "{%0,%1,%2,%3}, {%4,%5,%6,%7}, {%8,%9}, {%0,%1,%2,%3};"
        : "+f"(d.x), "+f"(d.y), "+f"(d.z), "+f"(d.w)
        : "r"(a0), "r"(a1), "r"(a2), "r"(a3), "r"(b0), "r"(b1));
}

__device__ __forceinline__ uint32_t smem_u32(const void* p) {
    uint32_t a;
    asm("{ .reg .u64 tmp; cvta.to.shared.u64 tmp, %1; cvt.u32.u64 %0, tmp; }"
        : "=r"(a) : "l"(p));
    return a;
}

__device__ __forceinline__ void cp16(uint32_t dst, const void* src) {
    asm volatile("cp.async.cg.shared.global [%0], [%1], 16;"
                 :: "r"(dst), "l"(src) : "memory");
}
#define CP_COMMIT() asm volatile("cp.async.commit_group;" ::: "memory")
#define CP_WAIT0()  asm volatile("cp.async.wait_group 0;" ::: "memory")
#define CP_WAIT2()  asm volatile("cp.async.wait_group 2;" ::: "memory")

// exp2 on the FMA pipe: degree-6 poly on f in [-0.5, 0.5], rel err ~1.2e-7.
__device__ __forceinline__ float exp2p(float x) {
    x = fmaxf(x, -126.0f);
    float n = rintf(x);
    float f = x - n;
    float p = 1.5403530e-4f;
    p = fmaf(p, f, 1.3333558e-3f);
    p = fmaf(p, f, 9.6181291e-3f);
    p = fmaf(p, f, 5.5504109e-2f);
    p = fmaf(p, f, 2.4022651e-1f);
    p = fmaf(p, f, 6.9314718e-1f);
    p = fmaf(p, f, 1.0f);
    float s = __int_as_float(((int)n + 127) << 23);
    return p * s;
}

// ============================================================================
// Pre-pass: tf32-round arrays (grid-stride, float4)
// ============================================================================
__global__ void round_pass(const float4* __restrict__ src,
                           float4* __restrict__ dst, int n4)
{
    int i = blockIdx.x * blockDim.x + threadIdx.x;
    int stride = gridDim.x * blockDim.x;
    for (; i < n4; i += stride) {
        float4 v = src[i];
        v.x = tf32_rna(v.x); v.y = tf32_rna(v.y);
        v.z = tf32_rna(v.z); v.w = tf32_rna(v.w);
        dst[i] = v;
    }
}

// ============================================================================
// TF32 warp-MMA GEMM core, cp.async 4-stage pipeline.
// C[128x128] of A[M,1024] @ B[N,1024]^T, inputs pre-rounded to tf32.
// 256 threads = 8 warps (2x4), warp tile 64x32, BK=16, one sync per chunk.
// Dynamic smem: A stages [4][128*20] then B stages [4][128*20] (80 KB).
// ============================================================================
#define KSTR 20
#define STGF (128*KSTR)
#define NSTG 4
#define BOFFS (NSTG*STGF)
#define GEMM_SMEM_BYTES (2*NSTG*STGF*4)   // 81920

__device__ __forceinline__ void gemm_fill(uint32_t smu, const float* __restrict__ Ab,
                                          const float* __restrict__ Bb,
                                          int stage, int chunk, int tid)
{
    const int row  = tid & 127;
    const int side = tid >> 7;
    const float* src = (side ? Bb : Ab) + (size_t)row * 1024 + chunk * 16;
    uint32_t dst = smu + (uint32_t)((side ? BOFFS : 0) + stage * STGF + row * KSTR) * 4;
    cp16(dst,      src);
    cp16(dst + 16, src + 4);
    cp16(dst + 32, src + 8);
    cp16(dst + 48, src + 12);
}

__device__ __forceinline__ void gemm_tf32_pipe(const float* __restrict__ A,
                                               const float* __restrict__ Bm,
                                               int m0, int n0, float4 acc[4][4])
{
    extern __shared__ float sm[];
    const uint32_t smu = smem_u32(sm);
    const int tid  = threadIdx.x;
    const int lane = tid & 31;
    const int warp = tid >> 5;
    const int wm = (warp >> 2) * 64;
    const int wn = (warp & 3) * 32;
    const int g  = lane >> 2;
    const int t  = lane & 3;

    const float* Ab = A  + (size_t)m0 * 1024;
    const float* Bb = Bm + (size_t)n0 * 1024;

#pragma unroll
    for (int am = 0; am < 4; am++)
#pragma unroll
        for (int an = 0; an < 4; an++)
            acc[am][an] = make_float4(0.f, 0.f, 0.f, 0.f);

    // prologue: stages 0..2 <- chunks 0..2
#pragma unroll
    for (int s = 0; s < NSTG - 1; s++) {
        gemm_fill(smu, Ab, Bb, s, s, tid);
        CP_COMMIT();
    }

    const int aOff = (wm + g) * KSTR + t;
    const int bOff = (wn + g) * KSTR + t;

    for (int c = 0; c < 64; ++c) {
        CP_WAIT2();            // chunk c resident
        __syncthreads();       // also: everyone finished reading stage (c-1)%4

        if (c + 3 < 64)
            gemm_fill(smu, Ab, Bb, (c + 3) & 3, c + 3, tid);
        CP_COMMIT();

        const float* as = sm + (c & 3) * STGF;
        const float* bs = sm + BOFFS + (c & 3) * STGF;
#pragma unroll
        for (int ks = 0; ks < 2; ++ks) {
            uint32_t af[4][4], bf[4][2];
#pragma unroll
            for (int am = 0; am < 4; am++) {
                const float* p = as + aOff + am * 16 * KSTR + ks * 8;
                af[am][0] = __float_as_uint(p[0]);
                af[am][1] = __float_as_uint(p[8 * KSTR]);
                af[am][2] = __float_as_uint(p[4]);
                af[am][3] = __float_as_uint(p[8 * KSTR + 4]);
            }
#pragma unroll
            for (int an = 0; an < 4; an++) {
                const float* p = bs + bOff + an * 8 * KSTR + ks * 8;
                bf[an][0] = __float_as_uint(p[0]);
                bf[an][1] = __float_as_uint(p[4]);
            }
#pragma unroll
            for (int am = 0; am < 4; am++)
#pragma unroll
                for (int an = 0; an < 4; an++)
                    mma_tf32(acc[am][an], af[am][0], af[am][1], af[am][2], af[am][3],
                             bf[an][0], bf[an][1]);
        }
    }
}

// ---------------------------------------------------------------------------
// Kernel 1: QKV GEMM. Epilogue scatters tf32-rounded Q/K/V; Q scaled by
// 0.125*log2(e) so attention scores come out in base-2 units.
// ---------------------------------------------------------------------------
#define QSCALE 0.18033688011112042f   // 0.125 * log2(e)

__global__ void __launch_bounds__(256, 2) qkv_mma()
{
    const int m0 = blockIdx.y * 128;
    const int n0 = blockIdx.x * 128;
    float4 acc[4][4];
    gemm_tf32_pipe(g_Xr, g_Wq, m0, n0, acc);

    const int lane = threadIdx.x & 31;
    const int warp = threadIdx.x >> 5;
    const int wm = (warp >> 2) * 64;
    const int wn = (warp & 3) * 32;
    const int g  = lane >> 2;
    const int t  = lane & 3;

#pragma unroll
    for (int an = 0; an < 4; an++) {
        const int ng  = n0 + wn + an * 8;        // n = h*192 + sel*64 + d
        const int grp = ng >> 6;
        const int h   = grp / 3;
        const int sel = grp - 3 * h;
        const int db  = (ng & 63) + t * 2;
        float* dst = (sel == 0) ? g_Q : ((sel == 1) ? g_K : g_V);
        const float sc = (sel == 0) ? QSCALE : 1.0f;
#pragma unroll
        for (int am = 0; am < 4; am++) {
#pragma unroll
            for (int half = 0; half < 2; half++) {
                const int m = m0 + wm + am * 16 + g + half * 8;
                const int b = m >> 11;
                const int s = m & 2047;
                float2 v;
                v.x = tf32_rna((half ? acc[am][an].z : acc[am][an].x) * sc);
                v.y = tf32_rna((half ? acc[am][an].w : acc[am][an].y) * sc);
                *(float2*)(dst + (((size_t)(b * 16 + h)) * 2048 + s) * 64 + db) = v;
            }
        }
    }
}

// ---------------------------------------------------------------------------
// Kernel 3: output projection.
// ---------------------------------------------------------------------------
__global__ void __launch_bounds__(256, 2) proj_mma(const float* __restrict__ bias,
                                                   float* __restrict__ out)
{
    const int m0 = blockIdx.y * 128;
    const int n0 = blockIdx.x * 128;
    float4 acc[4][4];
    gemm_tf32_pipe(g_O, g_Wp, m0, n0, acc);

    const int lane = threadIdx.x & 31;
    const int warp = threadIdx.x >> 5;
    const int wm = (warp >> 2) * 64;
    const int wn = (warp & 3) * 32;
    const int g  = lane >> 2;
    const int t  = lane & 3;

#pragma unroll
    for (int an = 0; an < 4; an++) {
        const int ng = n0 + wn + an * 8 + t * 2;
        const float2 bi = *(const float2*)(bias + ng);
#pragma unroll
        for (int am = 0; am < 4; am++) {
#pragma unroll
            for (int half = 0; half < 2; half++) {
                const int m = m0 + wm + am * 16 + g + half * 8;
                float2 v;
                v.x = (half ? acc[am][an].z : acc[am][an].x) + bi.x;
                v.y = (half ? acc[am][an].w : acc[am][an].y) + bi.y;
                *(float2*)(out + (size_t)m * 1024 + ng) = v;
            }
        }
    }
}

// ============================================================================
// Kernel 2: tensor-core causal flash attention (round-4 verified).
// CTA: 128 q-rows x 64 kv-tile, 8 warps, m16n8k8 tf32 MMAs, cp.async K/V.
// ============================================================================
#define KSTRD 68
#define VSTRD 72
#define KBUF  (64*KSTRD)
#define OFF_V (2*KBUF)
#define VBUF  (64*VSTRD)
#define OFF_P (OFF_V + 2*VBUF)
#define FA_SMEM_BYTES ((OFF_P + 128*KSTRD) * 4)   // 106496

__global__ void __launch_bounds__(256, 1) flash_attn_tc()
{
    extern __shared__ float sm[];
    const uint32_t smu = smem_u32(sm);
    const int tid  = threadIdx.x;
    const int lane = tid & 31;
    const int warp = tid >> 5;
    const int g  = lane >> 2;
    const int t4 = lane & 3;
    const int qt = 15 - (int)blockIdx.x;
    const int bh = blockIdx.y;
    const int q0 = qt * 128;
    const int wr = warp * 16;
    const int tmax = 2 * qt + 1;

    const float* Qg = g_Q + (size_t)bh * S_ * 64;
    const float* Kg = g_K + (size_t)bh * S_ * 64;
    const float* Vg = g_V + (size_t)bh * S_ * 64;

    {
        const int r = tid >> 2;
        const int c = (tid & 3) * 16;
        const float* ks = Kg + (size_t)r * 64 + c;
        const float* vs = Vg + (size_t)r * 64 + c;
        const uint32_t kd = smu + (uint32_t)(r * KSTRD + c) * 4;
        const uint32_t vd = smu + (uint32_t)(OFF_V + r * VSTRD + c) * 4;
#pragma unroll
        for (int j = 0; j < 4; j++) {
            cp16(kd + j * 16, ks + j * 4);
            cp16(vd + j * 16, vs + j * 4);
        }
        CP_COMMIT();
    }

    {
        const int r  = tid >> 1;
        const int c0 = (tid & 1) * 32;
        const float* src = Qg + (size_t)(q0 + r) * 64 + c0;
        float* dst = sm + OFF_P + r * KSTRD + c0;
#pragma unroll
        for (int j = 0; j < 8; j++)
            *(float4*)(dst + j * 4) = *(const float4*)(src + j * 4);
    }
    __syncthreads();

    uint32_t qf[8][4];
#pragma unroll
    for (int kk = 0; kk < 8; kk++) {
        const float* p = sm + OFF_P + (wr + g) * KSTRD + kk * 8 + t4;
        qf[kk][0] = __float_as_uint(p[0]);
        qf[kk][1] = __float_as_uint(p[8 * KSTRD]);
        qf[kk][2] = __float_as_uint(p[4]);
        qf[kk][3] = __float_as_uint(p[8 * KSTRD + 4]);
    }

    float m2[2] = {-1e30f, -1e30f};
    float l2[2] = {0.f, 0.f};
    float4 of[8];
#pragma unroll
    for (int an = 0; an < 8; an++) of[an] = make_float4(0.f, 0.f, 0.f, 0.f);

    for (int t = 0; t <= tmax; t++) {
        CP_WAIT0();
        __syncthreads();

        if (t < tmax) {
            const int kv1 = (t + 1) * 64;
            const int buf = (t + 1) & 1;
            const int r = tid >> 2;
            const int c = (tid & 3) * 16;
            const float* ks = Kg + (size_t)(kv1 + r) * 64 + c;
            const float* vs = Vg + (size_t)(kv1 + r) * 64 + c;
            const uint32_t kd = smu + (uint32_t)(buf * KBUF + r * KSTRD + c) * 4;
            const uint32_t vd = smu + (uint32_t)(OFF_V + buf * VBUF + r * VSTRD + c) * 4;
#pragma unroll
            for (int j = 0; j < 4; j++) {
                cp16(kd + j * 16, ks + j * 4);
                cp16(vd + j * 16, vs + j * 4);
            }
            CP_COMMIT();
        }

        const int kv0 = t * 64;
        if (kv0 <= q0 + wr + 15) {
            const float* smK = sm + (t & 1) * KBUF;
            const float* smV = sm + OFF_V + (t & 1) * VBUF;

            float4 sf[8];
#pragma unroll
            for (int an = 0; an < 8; an++) sf[an] = make_float4(0.f, 0.f, 0.f, 0.f);
#pragma unroll
            for (int kk = 0; kk < 8; kk++) {
#pragma unroll
                for (int an = 0; an < 8; an++) {
                    const float* bp = smK + (an * 8 + g) * KSTRD + kk * 8 + t4;
                    mma_tf32(sf[an], qf[kk][0], qf[kk][1], qf[kk][2], qf[kk][3],
                             __float_as_uint(bp[0]), __float_as_uint(bp[4]));
                }
            }

            if (kv0 + 63 > q0 + wr) {
                const int r0 = q0 + wr + g;
                const int r1 = r0 + 8;
#pragma unroll
                for (int an = 0; an < 8; an++) {
                    const int col = kv0 + an * 8 + 2 * t4;
                    if (col     > r0) sf[an].x = -1e30f;
                    if (col + 1 > r0) sf[an].y = -1e30f;
                    if (col     > r1) sf[an].z = -1e30f;
                    if (col + 1 > r1) sf[an].w = -1e30f;
                }
            }

            float mt0 = -1e30f, mt1 = -1e30f;
#pragma unroll
            for (int an = 0; an < 8; an++) {
                mt0 = fmaxf(mt0, fmaxf(sf[an].x, sf[an].y));
                mt1 = fmaxf(mt1, fmaxf(sf[an].z, sf[an].w));
            }
            mt0 = fmaxf(mt0, __shfl_xor_sync(0xffffffffu, mt0, 1));
            mt0 = fmaxf(mt0, __shfl_xor_sync(0xffffffffu, mt0, 2));
            mt1 = fmaxf(mt1, __shfl_xor_sync(0xffffffffu, mt1, 1));
            mt1 = fmaxf(mt1, __shfl_xor_sync(0xffffffffu, mt1, 2));

            const float mn0 = fmaxf(m2[0], mt0);
            const float mn1 = fmaxf(m2[1], mt1);
            const float a0 = exp2p(m2[0] - mn0);
            const float a1 = exp2p(m2[1] - mn1);
            m2[0] = mn0; m2[1] = mn1;

            float s0 = 0.f, s1 = 0.f;
#pragma unroll
            for (int an = 0; an < 8; an++) {
                sf[an].x = tf32_rna(exp2p(sf[an].x - mn0));
                sf[an].y = tf32_rna(exp2p(sf[an].y - mn0));
                sf[an].z = tf32_rna(exp2p(sf[an].z - mn1));
                sf[an].w = tf32_rna(exp2p(sf[an].w - mn1));
                s0 += sf[an].x + sf[an].y;
                s1 += sf[an].z + sf[an].w;
            }
            s0 += __shfl_xor_sync(0xffffffffu, s0, 1);
            s0 += __shfl_xor_sync(0xffffffffu, s0, 2);
            s1 += __shfl_xor_sync(0xffffffffu, s1, 1);
            s1 += __shfl_xor_sync(0xffffffffu, s1, 2);
            l2[0] = l2[0] * a0 + s0;
            l2[1] = l2[1] * a1 + s1;

#pragma unroll
            for (int an = 0; an < 8; an++) {
                of[an].x *= a0; of[an].y *= a0;
                of[an].z *= a1; of[an].w *= a1;
            }

            {
                float* pp = sm + OFF_P + (wr + g) * KSTRD;
#pragma unroll
                for (int an = 0; an < 8; an++) {
                    *(float2*)(pp + an * 8 + 2 * t4) = make_float2(sf[an].x, sf[an].y);
                    *(float2*)(pp + 8 * KSTRD + an * 8 + 2 * t4) = make_float2(sf[an].z, sf[an].w);
                }
            }
            __syncwarp();

#pragma unroll
            for (int kk = 0; kk < 8; kk++) {
                const float* ap = sm + OFF_P + (wr + g) * KSTRD + kk * 8 + t4;
                const uint32_t A0 = __float_as_uint(ap[0]);
                const uint32_t A1 = __float_as_uint(ap[8 * KSTRD]);
                const uint32_t A2 = __float_as_uint(ap[4]);
                const uint32_t A3 = __float_as_uint(ap[8 * KSTRD + 4]);
#pragma unroll
                for (int an = 0; an < 8; an++) {
                    const float* vp = smV + (kk * 8 + t4) * VSTRD + an * 8 + g;
                    mma_tf32(of[an], A0, A1, A2, A3,
                             __float_as_uint(vp[0]), __float_as_uint(vp[4 * VSTRD]));
                }
            }
        }
        __syncthreads();
    }

    // epilogue: normalize, tf32-round (proj A input), write (b, s, h*64+d)
    const int b = bh >> 4;
    const int h = bh & 15;
    const float i0 = 1.0f / l2[0];
    const float i1 = 1.0f / l2[1];
    const int r0 = q0 + wr + g;
    const int r1 = r0 + 8;
    float* o0 = g_O + ((size_t)b * 2048 + r0) * 1024 + h * 64;
    float* o1 = g_O + ((size_t)b * 2048 + r1) * 1024 + h * 64;
#pragma unroll
    for (int an = 0; an < 8; an++) {
        const int d = an * 8 + 2 * t4;
        *(float2*)(o0 + d) = make_float2(tf32_rna(of[an].x * i0), tf32_rna(of[an].y * i0));
        *(float2*)(o1 + d) = make_float2(tf32_rna(of[an].z * i1), tf32_rna(of[an].w * i1));
    }
}

// ---------------------------------------------------------------------------
extern "C" void kernel_launch(void* const* d_in, const int* in_sizes, int n_in,
                              void* d_out, int out_size)
{
    const float* x      = (const float*)d_in[0];  // (2,2048,1024)
    const float* w_qkv  = (const float*)d_in[1];  // (3072,1024)
    const float* w_proj = (const float*)d_in[2];  // (1024,1024)
    const float* b_proj = (const float*)d_in[3];  // (1024,)
    float* out = (float*)d_out;

    cudaFuncSetAttribute(flash_attn_tc, cudaFuncAttributeMaxDynamicSharedMemorySize,
                         FA_SMEM_BYTES);
    cudaFuncSetAttribute(qkv_mma, cudaFuncAttributeMaxDynamicSharedMemorySize,
                         GEMM_SMEM_BYTES);
    cudaFuncSetAttribute(proj_mma, cudaFuncAttributeMaxDynamicSharedMemorySize,
                         GEMM_SMEM_BYTES);

    float* xr; float* wq; float* wp;
    cudaGetSymbolAddress((void**)&xr, g_Xr);
    cudaGetSymbolAddress((void**)&wq, g_Wq);
    cudaGetSymbolAddress((void**)&wp, g_Wp);

    round_pass<<<512, 256>>>((const float4*)x,      (float4*)xr, (B_*S_*E_) / 4);
    round_pass<<<512, 256>>>((const float4*)w_qkv,  (float4*)wq, (3*E_*E_) / 4);
    round_pass<<<512, 256>>>((const float4*)w_proj, (float4*)wp, (E_*E_) / 4);

    qkv_mma<<<dim3(24, 32), 256, GEMM_SMEM_BYTES>>>();
    flash_attn_tc<<<dim3(16, 32), 256, FA_SMEM_BYTES>>>();
    proj_mma<<<dim3(8, 32), 256, GEMM_SMEM_BYTES>>>(b_proj, out);
}

// round 6
// speedup vs baseline: 1.1746x; 1.1746x over previous
#include <cuda_runtime.h>
#include <math.h>
#include <stdint.h>

#define B_  2
#define S_  2048
#define E_  1024
#define H_  16
#define HD_ 64

// Scratch (allocation-free: __device__ globals)
__device__ float g_Q[B_*H_*S_*HD_];   // tf32-rounded, pre-scaled by 0.125*log2(e)
__device__ float g_K[B_*H_*S_*HD_];   // tf32-rounded
__device__ float g_V[B_*H_*S_*HD_];   // tf32-rounded
__device__ float g_O[B_*S_*E_];       // attention out, tf32-rounded (proj A input)
__device__ float g_Xr[B_*S_*E_];      // tf32-rounded x
__device__ float g_Wq[3*E_*E_];       // tf32-rounded w_qkv
__device__ float g_Wp[E_*E_];         // tf32-rounded w_proj

// ============================================================================
// PTX helpers (plain sm_80+ ISA — no 'a'-suffix features)
// ============================================================================
__device__ __forceinline__ float tf32_rna(float x) {
    uint32_t r;
    asm("cvt.rna.tf32.f32 %0, %1;" : "=r"(r) : "f"(x));
    return __uint_as_float(r);
}

__device__ __forceinline__ void mma_tf32(float4& d,
                                         uint32_t a0, uint32_t a1, uint32_t a2, uint32_t a3,
                                         uint32_t b0, uint32_t b1)
{
    asm volatile(
        "mma.sync.aligned.m16n8k8.row.col.f32.tf32.tf32.f32 "
        "{%0,%1,%2,%3}, {%4,%5,%6,%7}, {%8,%9}, {%0,%1,%2,%3};"
        : "+f"(d.x), "+f"(d.y), "+f"(d.z), "+f"(d.w)
        : "r"(a0), "r"(a1), "r"(a2), "r"(a3), "r"(b0), "r"(b1));
}

__device__ __forceinline__ uint32_t smem_u32(const void* p) {
    uint32_t a;
    asm("{ .reg .u64 tmp; cvta.to.shared.u64 tmp, %1; cvt.u32.u64 %0, tmp; }"
        : "=r"(a) : "l"(p));
    return a;
}

__device__ __forceinline__ void cp16(uint32_t dst, const void* src) {
    asm volatile("cp.async.cg.shared.global [%0], [%1], 16;"
                 :: "r"(dst), "l"(src) : "memory");
}
#define CP_COMMIT() asm volatile("cp.async.commit_group;" ::: "memory")
#define CP_WAIT0()  asm volatile("cp.async.wait_group 0;" ::: "memory")
#define CP_WAIT2()  asm volatile("cp.async.wait_group 2;" ::: "memory")

// exp2 on the FMA pipe: degree-6 poly on f in [-0.5, 0.5], rel err ~1.2e-7.
__device__ __forceinline__ float exp2p(float x) {
    x = fmaxf(x, -126.0f);
    float n = rintf(x);
    float f = x - n;
    float p = 1.5403530e-4f;
    p = fmaf(p, f, 1.3333558e-3f);
    p = fmaf(p, f, 9.6181291e-3f);
    p = fmaf(p, f, 5.5504109e-2f);
    p = fmaf(p, f, 2.4022651e-1f);
    p = fmaf(p, f, 6.9314718e-1f);
    p = fmaf(p, f, 1.0f);
    float s = __int_as_float(((int)n + 127) << 23);
    return p * s;
}

// ============================================================================
// Pre-pass: tf32-round arrays (grid-stride, float4)
// ============================================================================
__global__ void round_pass(const float4* __restrict__ src,
                           float4* __restrict__ dst, int n4)
{
    int i = blockIdx.x * blockDim.x + threadIdx.x;
    int stride = gridDim.x * blockDim.x;
    for (; i < n4; i += stride) {
        float4 v = src[i];
        v.x = tf32_rna(v.x); v.y = tf32_rna(v.y);
        v.z = tf32_rna(v.z); v.w = tf32_rna(v.w);
        dst[i] = v;
    }
}

// ============================================================================
// TF32 warp-MMA GEMM, occupancy-first variant.
// CTA tile 128(M) x 64(N), 8 warps arranged 4(m) x 2(n): warp tile 32x32.
// 4-stage cp.async pipeline, BK=16. Stage = A[128][20] | B[64][20] = 15,360 B.
// 4 stages = 61,440 B -> 3 CTAs/SM; __launch_bounds__(256,3) caps regs at 85.
// acc: 2(am) x 4(an) float4 = 32 regs.
// ============================================================================
#define KSTR 20
#define STGF (192*KSTR)        // 3840 floats per stage (A:128 rows, B:64 rows)
#define BROW (128*KSTR)        // B rows start at float offset 2560 within stage
#define NSTG 4
#define GEMM_SMEM_BYTES (NSTG*STGF*4)   // 61440

__device__ __forceinline__ void gemm_fill(uint32_t smu, const float* __restrict__ Ab,
                                          const float* __restrict__ Bb,
                                          int stage, int chunk, int tid)
{
#pragma unroll
    for (int j = 0; j < 3; j++) {
        const int o = tid + 256 * j;      // 0..767
        const int r = o >> 2;             // 0..191
        const int q = (o & 3) * 4;        // float offset within the 16-float chunk
        const float* src;
        uint32_t off;
        if (r < 128) {
            src = Ab + (size_t)r * 1024 + chunk * 16 + q;
            off = (uint32_t)(stage * STGF + r * KSTR + q);
        } else {
            src = Bb + (size_t)(r - 128) * 1024 + chunk * 16 + q;
            off = (uint32_t)(stage * STGF + BROW + (r - 128) * KSTR + q);
        }
        cp16(smu + off * 4, src);
    }
}

__device__ __forceinline__ void gemm_tf32_pipe(const float* __restrict__ A,
                                               const float* __restrict__ Bm,
                                               int m0, int n0, float4 acc[2][4])
{
    extern __shared__ float sm[];
    const uint32_t smu = smem_u32(sm);
    const int tid  = threadIdx.x;
    const int lane = tid & 31;
    const int warp = tid >> 5;
    const int wm = (warp >> 1) * 32;   // 0,32,64,96
    const int wn = (warp & 1) * 32;    // 0,32
    const int g  = lane >> 2;
    const int t  = lane & 3;

    const float* Ab = A  + (size_t)m0 * 1024;
    const float* Bb = Bm + (size_t)n0 * 1024;

#pragma unroll
    for (int am = 0; am < 2; am++)
#pragma unroll
        for (int an = 0; an < 4; an++)
            acc[am][an] = make_float4(0.f, 0.f, 0.f, 0.f);

#pragma unroll
    for (int s = 0; s < NSTG - 1; s++) {
        gemm_fill(smu, Ab, Bb, s, s, tid);
        CP_COMMIT();
    }

    const int aOff = (wm + g) * KSTR + t;
    const int bOff = BROW + (wn + g) * KSTR + t;

    for (int c = 0; c < 64; ++c) {
        CP_WAIT2();            // chunk c resident
        __syncthreads();       // everyone finished reading stage (c-1)%4

        if (c + 3 < 64)
            gemm_fill(smu, Ab, Bb, (c + 3) & 3, c + 3, tid);
        CP_COMMIT();

        const float* st = sm + (c & 3) * STGF;

        // load ALL fragments for both k-steps first (max MLP), then 16 MMAs
        uint32_t af[2][2][4], bf[2][4][2];
#pragma unroll
        for (int ks = 0; ks < 2; ++ks) {
#pragma unroll
            for (int am = 0; am < 2; am++) {
                const float* p = st + aOff + am * 16 * KSTR + ks * 8;
                af[ks][am][0] = __float_as_uint(p[0]);
                af[ks][am][1] = __float_as_uint(p[8 * KSTR]);
                af[ks][am][2] = __float_as_uint(p[4]);
                af[ks][am][3] = __float_as_uint(p[8 * KSTR + 4]);
            }
#pragma unroll
            for (int an = 0; an < 4; an++) {
                const float* p = st + bOff + an * 8 * KSTR + ks * 8;
                bf[ks][an][0] = __float_as_uint(p[0]);
                bf[ks][an][1] = __float_as_uint(p[4]);
            }
        }
#pragma unroll
        for (int ks = 0; ks < 2; ++ks)
#pragma unroll
            for (int am = 0; am < 2; am++)
#pragma unroll
                for (int an = 0; an < 4; an++)
                    mma_tf32(acc[am][an],
                             af[ks][am][0], af[ks][am][1], af[ks][am][2], af[ks][am][3],
                             bf[ks][an][0], bf[ks][an][1]);
    }
}

// ---------------------------------------------------------------------------
// Kernel 1: QKV GEMM. grid (48, 32). Epilogue scatters tf32-rounded Q/K/V;
// Q scaled by 0.125*log2(e) so attention scores come out in base-2 units.
// ---------------------------------------------------------------------------
#define QSCALE 0.18033688011112042f   // 0.125 * log2(e)

__global__ void __launch_bounds__(256, 3) qkv_mma()
{
    const int m0 = blockIdx.y * 128;
    const int n0 = blockIdx.x * 64;
    float4 acc[2][4];
    gemm_tf32_pipe(g_Xr, g_Wq, m0, n0, acc);

    const int lane = threadIdx.x & 31;
    const int warp = threadIdx.x >> 5;
    const int wm = (warp >> 1) * 32;
    const int wn = (warp & 1) * 32;
    const int g  = lane >> 2;
    const int t  = lane & 3;

#pragma unroll
    for (int an = 0; an < 4; an++) {
        const int ng  = n0 + wn + an * 8;        // n = h*192 + sel*64 + d
        const int grp = ng >> 6;
        const int h   = grp / 3;
        const int sel = grp - 3 * h;
        const int db  = (ng & 63) + t * 2;
        float* dst = (sel == 0) ? g_Q : ((sel == 1) ? g_K : g_V);
        const float sc = (sel == 0) ? QSCALE : 1.0f;
#pragma unroll
        for (int am = 0; am < 2; am++) {
#pragma unroll
            for (int half = 0; half < 2; half++) {
                const int m = m0 + wm + am * 16 + g + half * 8;
                const int b = m >> 11;
                const int s = m & 2047;
                float2 v;
                v.x = tf32_rna((half ? acc[am][an].z : acc[am][an].x) * sc);
                v.y = tf32_rna((half ? acc[am][an].w : acc[am][an].y) * sc);
                *(float2*)(dst + (((size_t)(b * 16 + h)) * 2048 + s) * 64 + db) = v;
            }
        }
    }
}

// ---------------------------------------------------------------------------
// Kernel 3: output projection. grid (16, 32).
// ---------------------------------------------------------------------------
__global__ void __launch_bounds__(256, 3) proj_mma(const float* __restrict__ bias,
                                                   float* __restrict__ out)
{
    const int m0 = blockIdx.y * 128;
    const int n0 = blockIdx.x * 64;
    float4 acc[2][4];
    gemm_tf32_pipe(g_O, g_Wp, m0, n0, acc);

    const int lane = threadIdx.x & 31;
    const int warp = threadIdx.x >> 5;
    const int wm = (warp >> 1) * 32;
    const int wn = (warp & 1) * 32;
    const int g  = lane >> 2;
    const int t  = lane & 3;

#pragma unroll
    for (int an = 0; an < 4; an++) {
        const int ng = n0 + wn + an * 8 + t * 2;
        const float2 bi = *(const float2*)(bias + ng);
#pragma unroll
        for (int am = 0; am < 2; am++) {
#pragma unroll
            for (int half = 0; half < 2; half++) {
                const int m = m0 + wm + am * 16 + g + half * 8;
                float2 v;
                v.x = (half ? acc[am][an].z : acc[am][an].x) + bi.x;
                v.y = (half ? acc[am][an].w : acc[am][an].y) + bi.y;
                *(float2*)(out + (size_t)m * 1024 + ng) = v;
            }
        }
    }
}

// ============================================================================
// Kernel 2: tensor-core causal flash attention (round-4 verified, unchanged).
// ============================================================================
#define KSTRD 68
#define VSTRD 72
#define KBUF  (64*KSTRD)
#define OFF_V (2*KBUF)
#define VBUF  (64*VSTRD)
#define OFF_P (OFF_V + 2*VBUF)
#define FA_SMEM_BYTES ((OFF_P + 128*KSTRD) * 4)   // 106496

__global__ void __launch_bounds__(256, 1) flash_attn_tc()
{
    extern __shared__ float sm[];
    const uint32_t smu = smem_u32(sm);
    const int tid  = threadIdx.x;
    const int lane = tid & 31;
    const int warp = tid >> 5;
    const int g  = lane >> 2;
    const int t4 = lane & 3;
    const int qt = 15 - (int)blockIdx.x;
    const int bh = blockIdx.y;
    const int q0 = qt * 128;
    const int wr = warp * 16;
    const int tmax = 2 * qt + 1;

    const float* Qg = g_Q + (size_t)bh * S_ * 64;
    const float* Kg = g_K + (size_t)bh * S_ * 64;
    const float* Vg = g_V + (size_t)bh * S_ * 64;

    {
        const int r = tid >> 2;
        const int c = (tid & 3) * 16;
        const float* ks = Kg + (size_t)r * 64 + c;
        const float* vs = Vg + (size_t)r * 64 + c;
        const uint32_t kd = smu + (uint32_t)(r * KSTRD + c) * 4;
        const uint32_t vd = smu + (uint32_t)(OFF_V + r * VSTRD + c) * 4;
#pragma unroll
        for (int j = 0; j < 4; j++) {
            cp16(kd + j * 16, ks + j * 4);
            cp16(vd + j * 16, vs + j * 4);
        }
        CP_COMMIT();
    }

    {
        const int r  = tid >> 1;
        const int c0 = (tid & 1) * 32;
        const float* src = Qg + (size_t)(q0 + r) * 64 + c0;
        float* dst = sm + OFF_P + r * KSTRD + c0;
#pragma unroll
        for (int j = 0; j < 8; j++)
            *(float4*)(dst + j * 4) = *(const float4*)(src + j * 4);
    }
    __syncthreads();

    uint32_t qf[8][4];
#pragma unroll
    for (int kk = 0; kk < 8; kk++) {
        const float* p = sm + OFF_P + (wr + g) * KSTRD + kk * 8 + t4;
        qf[kk][0] = __float_as_uint(p[0]);
        qf[kk][1] = __float_as_uint(p[8 * KSTRD]);
        qf[kk][2] = __float_as_uint(p[4]);
        qf[kk][3] = __float_as_uint(p[8 * KSTRD + 4]);
    }

    float m2[2] = {-1e30f, -1e30f};
    float l2[2] = {0.f, 0.f};
    float4 of[8];
#pragma unroll
    for (int an = 0; an < 8; an++) of[an] = make_float4(0.f, 0.f, 0.f, 0.f);

    for (int t = 0; t <= tmax; t++) {
        CP_WAIT0();
        __syncthreads();

        if (t < tmax) {
            const int kv1 = (t + 1) * 64;
            const int buf = (t + 1) & 1;
            const int r = tid >> 2;
            const int c = (tid & 3) * 16;
            const float* ks = Kg + (size_t)(kv1 + r) * 64 + c;
            const float* vs = Vg + (size_t)(kv1 + r) * 64 + c;
            const uint32_t kd = smu + (uint32_t)(buf * KBUF + r * KSTRD + c) * 4;
            const uint32_t vd = smu + (uint32_t)(OFF_V + buf * VBUF + r * VSTRD + c) * 4;
#pragma unroll
            for (int j = 0; j < 4; j++) {
                cp16(kd + j * 16, ks + j * 4);
                cp16(vd + j * 16, vs + j * 4);
            }
            CP_COMMIT();
        }

        const int kv0 = t * 64;
        if (kv0 <= q0 + wr + 15) {
            const float* smK = sm + (t & 1) * KBUF;
            const float* smV = sm + OFF_V + (t & 1) * VBUF;

            float4 sf[8];
#pragma unroll
            for (int an = 0; an < 8; an++) sf[an] = make_float4(0.f, 0.f, 0.f, 0.f);
#pragma unroll
            for (int kk = 0; kk < 8; kk++) {
#pragma unroll
                for (int an = 0; an < 8; an++) {
                    const float* bp = smK + (an * 8 + g) * KSTRD + kk * 8 + t4;
                    mma_tf32(sf[an], qf[kk][0], qf[kk][1], qf[kk][2], qf[kk][3],
                             __float_as_uint(bp[0]), __float_as_uint(bp[4]));
                }
            }

            if (kv0 + 63 > q0 + wr) {
                const int r0 = q0 + wr + g;
                const int r1 = r0 + 8;
#pragma unroll
                for (int an = 0; an < 8; an++) {
                    const int col = kv0 + an * 8 + 2 * t4;
                    if (col     > r0) sf[an].x = -1e30f;
                    if (col + 1 > r0) sf[an].y = -1e30f;
                    if (col     > r1) sf[an].z = -1e30f;
                    if (col + 1 > r1) sf[an].w = -1e30f;
                }
            }

            float mt0 = -1e30f, mt1 = -1e30f;
#pragma unroll
            for (int an = 0; an < 8; an++) {
                mt0 = fmaxf(mt0, fmaxf(sf[an].x, sf[an].y));
                mt1 = fmaxf(mt1, fmaxf(sf[an].z, sf[an].w));
            }
            mt0 = fmaxf(mt0, __shfl_xor_sync(0xffffffffu, mt0, 1));
            mt0 = fmaxf(mt0, __shfl_xor_sync(0xffffffffu, mt0, 2));
            mt1 = fmaxf(mt1, __shfl_xor_sync(0xffffffffu, mt1, 1));
            mt1 = fmaxf(mt1, __shfl_xor_sync(0xffffffffu, mt1, 2));

            const float mn0 = fmaxf(m2[0], mt0);
            const float mn1 = fmaxf(m2[1], mt1);
            const float a0 = exp2p(m2[0] - mn0);
            const float a1 = exp2p(m2[1] - mn1);
            m2[0] = mn0; m2[1] = mn1;

            float s0 = 0.f, s1 = 0.f;
#pragma unroll
            for (int an = 0; an < 8; an++) {
                sf[an].x = tf32_rna(exp2p(sf[an].x - mn0));
                sf[an].y = tf32_rna(exp2p(sf[an].y - mn0));
                sf[an].z = tf32_rna(exp2p(sf[an].z - mn1));
                sf[an].w = tf32_rna(exp2p(sf[an].w - mn1));
                s0 += sf[an].x + sf[an].y;
                s1 += sf[an].z + sf[an].w;
            }
            s0 += __shfl_xor_sync(0xffffffffu, s0, 1);
            s0 += __shfl_xor_sync(0xffffffffu, s0, 2);
            s1 += __shfl_xor_sync(0xffffffffu, s1, 1);
            s1 += __shfl_xor_sync(0xffffffffu, s1, 2);
            l2[0] = l2[0] * a0 + s0;
            l2[1] = l2[1] * a1 + s1;

#pragma unroll
            for (int an = 0; an < 8; an++) {
                of[an].x *= a0; of[an].y *= a0;
                of[an].z *= a1; of[an].w *= a1;
            }

            {
                float* pp = sm + OFF_P + (wr + g) * KSTRD;
#pragma unroll
                for (int an = 0; an < 8; an++) {
                    *(float2*)(pp + an * 8 + 2 * t4) = make_float2(sf[an].x, sf[an].y);
                    *(float2*)(pp + 8 * KSTRD + an * 8 + 2 * t4) = make_float2(sf[an].z, sf[an].w);
                }
            }
            __syncwarp();

#pragma unroll
            for (int kk = 0; kk < 8; kk++) {
                const float* ap = sm + OFF_P + (wr + g) * KSTRD + kk * 8 + t4;
                const uint32_t A0 = __float_as_uint(ap[0]);
                const uint32_t A1 = __float_as_uint(ap[8 * KSTRD]);
                const uint32_t A2 = __float_as_uint(ap[4]);
                const uint32_t A3 = __float_as_uint(ap[8 * KSTRD + 4]);
#pragma unroll
                for (int an = 0; an < 8; an++) {
                    const float* vp = smV + (kk * 8 + t4) * VSTRD + an * 8 + g;
                    mma_tf32(of[an], A0, A1, A2, A3,
                             __float_as_uint(vp[0]), __float_as_uint(vp[4 * VSTRD]));
                }
            }
        }
        __syncthreads();
    }

    const int b = bh >> 4;
    const int h = bh & 15;
    const float i0 = 1.0f / l2[0];
    const float i1 = 1.0f / l2[1];
    const int r0 = q0 + wr + g;
    const int r1 = r0 + 8;
    float* o0 = g_O + ((size_t)b * 2048 + r0) * 1024 + h * 64;
    float* o1 = g_O + ((size_t)b * 2048 + r1) * 1024 + h * 64;
#pragma unroll
    for (int an = 0; an < 8; an++) {
        const int d = an * 8 + 2 * t4;
        *(float2*)(o0 + d) = make_float2(tf32_rna(of[an].x * i0), tf32_rna(of[an].y * i0));
        *(float2*)(o1 + d) = make_float2(tf32_rna(of[an].z * i1), tf32_rna(of[an].w * i1));
    }
}

// ---------------------------------------------------------------------------
extern "C" void kernel_launch(void* const* d_in, const int* in_sizes, int n_in,
                              void* d_out, int out_size)
{
    const float* x      = (const float*)d_in[0];  // (2,2048,1024)
    const float* w_qkv  = (const float*)d_in[1];  // (3072,1024)
    const float* w_proj = (const float*)d_in[2];  // (1024,1024)
    const float* b_proj = (const float*)d_in[3];  // (1024,)
    float* out = (float*)d_out;

    cudaFuncSetAttribute(flash_attn_tc, cudaFuncAttributeMaxDynamicSharedMemorySize,
                         FA_SMEM_BYTES);
    cudaFuncSetAttribute(qkv_mma, cudaFuncAttributeMaxDynamicSharedMemorySize,
                         GEMM_SMEM_BYTES);
    cudaFuncSetAttribute(proj_mma, cudaFuncAttributeMaxDynamicSharedMemorySize,
                         GEMM_SMEM_BYTES);

    float* xr; float* wq; float* wp;
    cudaGetSymbolAddress((void**)&xr, g_Xr);
    cudaGetSymbolAddress((void**)&wq, g_Wq);
    cudaGetSymbolAddress((void**)&wp, g_Wp);

    round_pass<<<512, 256>>>((const float4*)x,      (float4*)xr, (B_*S_*E_) / 4);
    round_pass<<<512, 256>>>((const float4*)w_qkv,  (float4*)wq, (3*E_*E_) / 4);
    round_pass<<<512, 256>>>((const float4*)w_proj, (float4*)wp, (E_*E_) / 4);

    qkv_mma<<<dim3(48, 32), 256, GEMM_SMEM_BYTES>>>();
    flash_attn_tc<<<dim3(16, 32), 256, FA_SMEM_BYTES>>>();
    proj_mma<<<dim3(16, 32), 256, GEMM_SMEM_BYTES>>>(b_proj, out);
}